// round 9
// baseline (speedup 1.0000x reference)
#include <cuda_runtime.h>
#include <cuda_bf16.h>
#include <cstdint>

#define SEQ 2048
#define DIM 512
#define QT  32
#define KT  32
#define NT_ 256
#define NIT (SEQ / KT)

#define QS32 260      // word stride of bf16-pair rows (260 % 32 == 4)
#define KBW  8320     // words per 32x260 tile
#define SPST 36       // float stride of partial-score rows
#define PS   20       // word stride of P pair rows

// smem word offsets
#define W_B0H 0
#define W_B0L 8320
#define W_B1H 16640
#define W_B1L 24960
#define W_QL  33280   // persistent Q-lo tile
#define W_SP  41600   // 4 x (32*36) = 4608
#define W_P0  46208   // 640
#define W_P1  46848   // 640
#define W_M   47488
#define W_L   47520
#define W_SC  47552
#define SMEM_WORDS 47584
#define SMEM_BYTES (SMEM_WORDS * 4)   // 190,336 B

__device__ __forceinline__ uint32_t smem_u32(const void* p) {
    uint32_t a;
    asm("{ .reg .u64 t; cvta.to.shared.u64 t, %1; cvt.u32.u64 %0, t; }" : "=r"(a) : "l"(p));
    return a;
}

__device__ __forceinline__ void cvt2(float x, float y, uint32_t& hip, uint32_t& lop) {
    __nv_bfloat16 bx = __float2bfloat16_rn(x);
    __nv_bfloat16 by = __float2bfloat16_rn(y);
    float rx = x - __bfloat162float(bx);
    float ry = y - __bfloat162float(by);
    __nv_bfloat162 h; h.x = bx; h.y = by;
    __nv_bfloat162 l; l.x = __float2bfloat16_rn(rx); l.y = __float2bfloat16_rn(ry);
    hip = *reinterpret_cast<uint32_t*>(&h);
    lop = *reinterpret_cast<uint32_t*>(&l);
}

__device__ __forceinline__ void mma16(float4& d,
                                      uint32_t a0, uint32_t a1, uint32_t a2, uint32_t a3,
                                      uint32_t b0, uint32_t b1) {
    asm volatile(
        "mma.sync.aligned.m16n8k16.row.col.f32.bf16.bf16.f32 "
        "{%0,%1,%2,%3},{%4,%5,%6,%7},{%8,%9},{%0,%1,%2,%3};"
        : "+f"(d.x), "+f"(d.y), "+f"(d.z), "+f"(d.w)
        : "r"(a0), "r"(a1), "r"(a2), "r"(a3), "r"(b0), "r"(b1));
}

__device__ __forceinline__ void ldsm4(uint32_t& r0, uint32_t& r1, uint32_t& r2, uint32_t& r3,
                                      uint32_t a) {
    asm volatile("ldmatrix.sync.aligned.m8n8.x4.shared.b16 {%0,%1,%2,%3}, [%4];"
                 : "=r"(r0), "=r"(r1), "=r"(r2), "=r"(r3) : "r"(a));
}
__device__ __forceinline__ void ldsm4t(uint32_t& r0, uint32_t& r1, uint32_t& r2, uint32_t& r3,
                                       uint32_t a) {
    asm volatile("ldmatrix.sync.aligned.m8n8.x4.trans.shared.b16 {%0,%1,%2,%3}, [%4];"
                 : "=r"(r0), "=r"(r1), "=r"(r2), "=r"(r3) : "r"(a));
}

__global__ void __launch_bounds__(NT_, 1)
attn_flash_v9(const float* __restrict__ enc,
              const float* __restrict__ dec,
              float* __restrict__ out) {
    extern __shared__ uint32_t sm[];
    float* fM  = (float*)(sm + W_M);
    float* fL  = (float*)(sm + W_L);
    float* fSc = (float*)(sm + W_SC);

    const uint32_t sb = smem_u32(sm);
    const int tid  = threadIdx.x;
    const int lane = tid & 31;
    const int wid  = tid >> 5;           // 0..7
    const bool isS = (wid < 4);
    const int g   = lane >> 2;
    const int t   = lane & 3;
    const int l16 = lane & 15;
    const int lhi = lane >> 4;
    const int l8  = lane & 7;
    const int mi  = lane >> 3;

    const int b  = blockIdx.x >> 6;
    const int q0 = (blockIdx.x & 63) * QT;
    const float* decb = dec + ((size_t)b * SEQ + q0) * DIM;
    const float* encb = enc + (size_t)b * SEQ * DIM;

    // ---- prologue: Q -> hi staged in buf1H, lo persistent in W_QL ----
#pragma unroll
    for (int j = 0; j < 16; j++) {
        int i  = tid + j * NT_;
        int r  = i >> 7;
        int c4 = (i & 127) << 2;
        float4 v = *(const float4*)(decb + r * DIM + c4);
        uint32_t h0, l0, h1, l1;
        cvt2(v.x, v.y, h0, l0);
        cvt2(v.z, v.w, h1, l1);
        uint32_t w = r * QS32 + (c4 >> 1);
        *(uint2*)(sm + W_B1H + w) = make_uint2(h0, h1);
        *(uint2*)(sm + W_QL  + w) = make_uint2(l0, l1);
    }
    if (tid < QT) { fM[tid] = -1e30f; fL[tid] = 0.0f; }
    __syncthreads();

    // ---- extract Q-hi fragments (S-warps), load K(0) -> buf0 (all) ----
    uint32_t qh[2][8][4];
    if (isS) {
#pragma unroll
        for (int mt = 0; mt < 2; mt++) {
            uint32_t aQh = sb + 4u * (W_B1H + (mt * 16 + l16) * QS32) + wid * 256 + lhi * 16;
#pragma unroll
            for (int s = 0; s < 8; s++)
                ldsm4(qh[mt][s][0], qh[mt][s][1], qh[mt][s][2], qh[mt][s][3], aQh + s * 32);
        }
    }
#pragma unroll
    for (int j = 0; j < 16; j++) {
        int i  = tid + j * NT_;
        int r  = i >> 7;
        int c4 = (i & 127) << 2;
        float4 v = *(const float4*)(encb + (size_t)r * DIM + c4);
        uint32_t h0, l0, h1, l1;
        cvt2(v.x, v.y, h0, l0);
        cvt2(v.z, v.w, h1, l1);
        uint32_t w = r * QS32 + (c4 >> 1);
        *(uint2*)(sm + W_B0H + w) = make_uint2(h0, h1);
        *(uint2*)(sm + W_B0L + w) = make_uint2(l0, l1);
    }
    __syncthreads();

    // O-group state
    float4 o[2][16];
#pragma unroll
    for (int mt = 0; mt < 2; mt++)
#pragma unroll
        for (int nt = 0; nt < 16; nt++) o[mt][nt] = make_float4(0.f, 0.f, 0.f, 0.f);
    const int nb2 = (wid - 4) * 128;     // O-warp column slice (valid for O warps)
    const uint32_t aP0 = sb + 4u * (W_P0 + l16 * PS) + lhi * 16;
    const uint32_t aP1 = aP0 + 4u * (W_P1 - W_P0);

    // GEMM2 + rescale for source iteration `src` (O-warps only)
    auto do_gemm2 = [&](int src) {
        const uint32_t kb2 = sb + ((src & 1) ? (uint32_t)(W_B1H * 4) : 0u);
        float sc[4];
#pragma unroll
        for (int j = 0; j < 4; j++) sc[j] = fSc[g + 8 * j];
#pragma unroll
        for (int mt = 0; mt < 2; mt++) {
            float slo = sc[2 * mt], shi = sc[2 * mt + 1];
#pragma unroll
            for (int nt = 0; nt < 16; nt++) {
                o[mt][nt].x *= slo; o[mt][nt].y *= slo;
                o[mt][nt].z *= shi; o[mt][nt].w *= shi;
            }
        }
        uint32_t A0[2][2][4], A1[2][2][4];
#pragma unroll
        for (int mt = 0; mt < 2; mt++)
#pragma unroll
            for (int ks = 0; ks < 2; ks++) {
                uint32_t off = (uint32_t)(mt * 16 * PS + ks * 8) * 4;
                ldsm4(A0[mt][ks][0], A0[mt][ks][1], A0[mt][ks][2], A0[mt][ks][3], aP0 + off);
                ldsm4(A1[mt][ks][0], A1[mt][ks][1], A1[mt][ks][2], A1[mt][ks][3], aP1 + off);
            }
        uint32_t aE0 = kb2 + 4u * (l16 * QS32) + (uint32_t)nb2 * 2 + lhi * 16;
        uint32_t aE1 = aE0 + 4u * KBW;
#pragma unroll
        for (int ks = 0; ks < 2; ks++) {
            uint32_t eoff = (uint32_t)(ks * 16 * QS32) * 4;
#pragma unroll
            for (int ntp = 0; ntp < 8; ntp++) {
                uint32_t bh0, bh1, bh2, bh3, bl0, bl1, bl2, bl3;
                ldsm4t(bh0, bh1, bh2, bh3, aE0 + eoff + ntp * 32);
                ldsm4t(bl0, bl1, bl2, bl3, aE1 + eoff + ntp * 32);
                int n0 = ntp * 2, n1 = n0 + 1;
#pragma unroll
                for (int mt = 0; mt < 2; mt++) {
                    mma16(o[mt][n0], A0[mt][ks][0], A0[mt][ks][1], A0[mt][ks][2], A0[mt][ks][3], bl0, bl1);
                    mma16(o[mt][n0], A1[mt][ks][0], A1[mt][ks][1], A1[mt][ks][2], A1[mt][ks][3], bh0, bh1);
                    mma16(o[mt][n0], A0[mt][ks][0], A0[mt][ks][1], A0[mt][ks][2], A0[mt][ks][3], bh0, bh1);
                    mma16(o[mt][n1], A0[mt][ks][0], A0[mt][ks][1], A0[mt][ks][2], A0[mt][ks][3], bl2, bl3);
                    mma16(o[mt][n1], A1[mt][ks][0], A1[mt][ks][1], A1[mt][ks][2], A1[mt][ks][3], bh2, bh3);
                    mma16(o[mt][n1], A0[mt][ks][0], A0[mt][ks][1], A0[mt][ks][2], A0[mt][ks][3], bh2, bh3);
                }
            }
        }
    };

    // half-K loader: 16 rows starting at rbase, by 128 threads (ltid 0..127)
    auto loadK = [&](const float* kg, uint32_t* kd, int ltid, int rbase) {
#pragma unroll
        for (int j = 0; j < 16; j++) {
            int r = rbase + j;
            int c = ltid << 2;
            float4 v = *(const float4*)(kg + (size_t)r * DIM + c);
            uint32_t h0, l0, h1, l1;
            cvt2(v.x, v.y, h0, l0);
            cvt2(v.z, v.w, h1, l1);
            uint32_t w = r * QS32 + (ltid << 1);
            *(uint2*)(kd + w) = make_uint2(h0, h1);
            *(uint2*)(kd + KBW + w) = make_uint2(l0, l1);
        }
    };

    for (int it = 0; it < NIT; it++) {
        // ---------- phase1: GEMM1(it) [S]  ||  GEMM2(it-1) [O] ----------
        if (isS) {
            const uint32_t kb = sb + ((it & 1) ? (uint32_t)(W_B1H * 4) : 0u);
            uint32_t aBhA = kb + 4u * (((mi >> 1) * 8 + l8) * QS32) + wid * 256 + (mi & 1) * 16;
            uint32_t aBhB = aBhA + 16u * QS32 * 4;
            uint32_t aBlA = aBhA + 4u * KBW;
            uint32_t aBlB = aBhB + 4u * KBW;
            uint32_t aQl0 = sb + 4u * (W_QL + l16 * QS32) + wid * 256 + lhi * 16;
            uint32_t aQl1 = aQl0 + 16u * QS32 * 4;
            float4 cH[2][4], cX[2][4];
#pragma unroll
            for (int mt = 0; mt < 2; mt++)
#pragma unroll
                for (int j = 0; j < 4; j++) {
                    cH[mt][j] = make_float4(0.f, 0.f, 0.f, 0.f);
                    cX[mt][j] = make_float4(0.f, 0.f, 0.f, 0.f);
                }
#pragma unroll
            for (int s = 0; s < 8; s++) {
                uint32_t bh0, bh1, bh2, bh3, bh4, bh5, bh6, bh7;
                uint32_t bl0, bl1, bl2, bl3, bl4, bl5, bl6, bl7;
                uint32_t ql0[4], ql1[4];
                ldsm4(bh0, bh1, bh2, bh3, aBhA + s * 32);
                ldsm4(bh4, bh5, bh6, bh7, aBhB + s * 32);
                ldsm4(bl0, bl1, bl2, bl3, aBlA + s * 32);
                ldsm4(bl4, bl5, bl6, bl7, aBlB + s * 32);
                ldsm4(ql0[0], ql0[1], ql0[2], ql0[3], aQl0 + s * 32);
                ldsm4(ql1[0], ql1[1], ql1[2], ql1[3], aQl1 + s * 32);
                mma16(cH[0][0], qh[0][s][0], qh[0][s][1], qh[0][s][2], qh[0][s][3], bh0, bh1);
                mma16(cH[0][1], qh[0][s][0], qh[0][s][1], qh[0][s][2], qh[0][s][3], bh2, bh3);
                mma16(cH[0][2], qh[0][s][0], qh[0][s][1], qh[0][s][2], qh[0][s][3], bh4, bh5);
                mma16(cH[0][3], qh[0][s][0], qh[0][s][1], qh[0][s][2], qh[0][s][3], bh6, bh7);
                mma16(cH[1][0], qh[1][s][0], qh[1][s][1], qh[1][s][2], qh[1][s][3], bh0, bh1);
                mma16(cH[1][1], qh[1][s][0], qh[1][s][1], qh[1][s][2], qh[1][s][3], bh2, bh3);
                mma16(cH[1][2], qh[1][s][0], qh[1][s][1], qh[1][s][2], qh[1][s][3], bh4, bh5);
                mma16(cH[1][3], qh[1][s][0], qh[1][s][1], qh[1][s][2], qh[1][s][3], bh6, bh7);
                mma16(cX[0][0], qh[0][s][0], qh[0][s][1], qh[0][s][2], qh[0][s][3], bl0, bl1);
                mma16(cX[0][1], qh[0][s][0], qh[0][s][1], qh[0][s][2], qh[0][s][3], bl2, bl3);
                mma16(cX[0][2], qh[0][s][0], qh[0][s][1], qh[0][s][2], qh[0][s][3], bl4, bl5);
                mma16(cX[0][3], qh[0][s][0], qh[0][s][1], qh[0][s][2], qh[0][s][3], bl6, bl7);
                mma16(cX[1][0], qh[1][s][0], qh[1][s][1], qh[1][s][2], qh[1][s][3], bl0, bl1);
                mma16(cX[1][1], qh[1][s][0], qh[1][s][1], qh[1][s][2], qh[1][s][3], bl2, bl3);
                mma16(cX[1][2], qh[1][s][0], qh[1][s][1], qh[1][s][2], qh[1][s][3], bl4, bl5);
                mma16(cX[1][3], qh[1][s][0], qh[1][s][1], qh[1][s][2], qh[1][s][3], bl6, bl7);
                mma16(cX[0][0], ql0[0], ql0[1], ql0[2], ql0[3], bh0, bh1);
                mma16(cX[0][1], ql0[0], ql0[1], ql0[2], ql0[3], bh2, bh3);
                mma16(cX[0][2], ql0[0], ql0[1], ql0[2], ql0[3], bh4, bh5);
                mma16(cX[0][3], ql0[0], ql0[1], ql0[2], ql0[3], bh6, bh7);
                mma16(cX[1][0], ql1[0], ql1[1], ql1[2], ql1[3], bh0, bh1);
                mma16(cX[1][1], ql1[0], ql1[1], ql1[2], ql1[3], bh2, bh3);
                mma16(cX[1][2], ql1[0], ql1[1], ql1[2], ql1[3], bh4, bh5);
                mma16(cX[1][3], ql1[0], ql1[1], ql1[2], ql1[3], bh6, bh7);
            }
            float* sp = (float*)(sm + W_SP + wid * 1152);
#pragma unroll
            for (int mt = 0; mt < 2; mt++) {
                int rr = mt * 16 + g;
#pragma unroll
                for (int j = 0; j < 4; j++) {
                    int cc = j * 8 + (t << 1);
                    *(float2*)(sp + rr * SPST + cc) =
                        make_float2(cH[mt][j].x + cX[mt][j].x, cH[mt][j].y + cX[mt][j].y);
                    *(float2*)(sp + (rr + 8) * SPST + cc) =
                        make_float2(cH[mt][j].z + cX[mt][j].z, cH[mt][j].w + cX[mt][j].w);
                }
            }
        } else {
            if (it > 0) do_gemm2(it - 1);
        }
        __syncthreads();

        // ---------- phase2: softmax(it) [S] + K(it+1) halves [S+O] ----------
        {
            const bool more = (it + 1 < NIT);
            uint32_t* kd = sm + (((it + 1) & 1) ? W_B1H : W_B0H);
            const float* kgn = encb + (size_t)(it + 1) * KT * DIM;
            if (isS) {
                int row = tid >> 2;          // 0..31
                int q   = tid & 3;
                const float* spb = (const float*)(sm + W_SP) + row * SPST + q * 8;
                float4 a0 = *(const float4*)(spb);
                float4 a1 = *(const float4*)(spb + 4);
                float4 b0_ = *(const float4*)(spb + 1152);
                float4 b1_ = *(const float4*)(spb + 1156);
                float4 c0_ = *(const float4*)(spb + 2304);
                float4 c1_ = *(const float4*)(spb + 2308);
                float4 d0_ = *(const float4*)(spb + 3456);
                float4 d1_ = *(const float4*)(spb + 3460);
                float s0 = (a0.x + b0_.x) + (c0_.x + d0_.x);
                float s1 = (a0.y + b0_.y) + (c0_.y + d0_.y);
                float s2 = (a0.z + b0_.z) + (c0_.z + d0_.z);
                float s3 = (a0.w + b0_.w) + (c0_.w + d0_.w);
                float s4 = (a1.x + b1_.x) + (c1_.x + d1_.x);
                float s5 = (a1.y + b1_.y) + (c1_.y + d1_.y);
                float s6 = (a1.z + b1_.z) + (c1_.z + d1_.z);
                float s7 = (a1.w + b1_.w) + (c1_.w + d1_.w);
                float mx = fmaxf(fmaxf(fmaxf(s0, s1), fmaxf(s2, s3)),
                                 fmaxf(fmaxf(s4, s5), fmaxf(s6, s7)));
                mx = fmaxf(mx, __shfl_xor_sync(0xffffffffu, mx, 1));
                mx = fmaxf(mx, __shfl_xor_sync(0xffffffffu, mx, 2));
                float mo = fM[row];
                float mn = fmaxf(mo, mx);
                float p0 = __expf(s0 - mn), p1 = __expf(s1 - mn);
                float p2 = __expf(s2 - mn), p3 = __expf(s3 - mn);
                float p4 = __expf(s4 - mn), p5 = __expf(s5 - mn);
                float p6 = __expf(s6 - mn), p7 = __expf(s7 - mn);
                float su = ((p0 + p1) + (p2 + p3)) + ((p4 + p5) + (p6 + p7));
                su += __shfl_xor_sync(0xffffffffu, su, 1);
                su += __shfl_xor_sync(0xffffffffu, su, 2);
                if (q == 0) {
                    float sc = __expf(mo - mn);
                    fSc[row] = sc;
                    fM[row]  = mn;
                    fL[row]  = fL[row] * sc + su;
                }
                uint32_t h[4], l[4];
                cvt2(p0, p1, h[0], l[0]);
                cvt2(p2, p3, h[1], l[1]);
                cvt2(p4, p5, h[2], l[2]);
                cvt2(p6, p7, h[3], l[3]);
                uint32_t w = row * PS + q * 4;
                *(uint4*)(sm + W_P0 + w) = make_uint4(h[0], h[1], h[2], h[3]);
                *(uint4*)(sm + W_P1 + w) = make_uint4(l[0], l[1], l[2], l[3]);
                if (more) loadK(kgn, kd, tid, 0);
            } else {
                if (more) loadK(kgn, kd, tid - 128, 16);
            }
        }
        __syncthreads();
    }

    // ---------- tail: final GEMM2 + epilogue (O-warps) ----------
    if (!isS) {
        do_gemm2(NIT - 1);
        float il[4];
#pragma unroll
        for (int j = 0; j < 4; j++) il[j] = 1.0f / fL[g + 8 * j];
        float* ob = out + ((size_t)b * SEQ + q0) * DIM;
#pragma unroll
        for (int mt = 0; mt < 2; mt++) {
            float ilo = il[2 * mt], ihi = il[2 * mt + 1];
            int r = mt * 16 + g;
#pragma unroll
            for (int nt = 0; nt < 16; nt++) {
                int c = nb2 + nt * 8 + (t << 1);
                float2 v0 = make_float2(o[mt][nt].x * ilo, o[mt][nt].y * ilo);
                float2 v1 = make_float2(o[mt][nt].z * ihi, o[mt][nt].w * ihi);
                *(float2*)(ob + r * DIM + c)       = v0;
                *(float2*)(ob + (r + 8) * DIM + c) = v1;
            }
        }
    }
}

extern "C" void kernel_launch(void* const* d_in, const int* in_sizes, int n_in,
                              void* d_out, int out_size) {
    const float* enc = (const float*)d_in[0];   // enc_outputs [8,2048,512]
    const float* dec = (const float*)d_in[1];   // dec_outputs [8,2048,512]
    float* out = (float*)d_out;                 // [8,2048,512]

    cudaFuncSetAttribute(attn_flash_v9,
                         cudaFuncAttributeMaxDynamicSharedMemorySize, SMEM_BYTES);

    dim3 grid(8 * (SEQ / QT));   // 512 CTAs, 1 per SM
    attn_flash_v9<<<grid, NT_, SMEM_BYTES>>>(enc, dec, out);
}

// round 10
// speedup vs baseline: 1.0053x; 1.0053x over previous
#include <cuda_runtime.h>
#include <cuda_bf16.h>
#include <cstdint>

#define SEQ 2048
#define DIM 512
#define QT  32
#define KT  32
#define NT_ 256
#define NIT (SEQ / KT)

#define QS32 260      // word stride of bf16-pair rows (260 % 32 == 4)
#define KBW  8320     // words per 32x260 tile
#define SPST 36       // float stride of partial-score rows
#define PS   20       // word stride of P pair rows

// smem word offsets
#define W_B0H 0
#define W_B0L 8320
#define W_B1H 16640
#define W_B1L 24960
#define W_RAW 33280   // raw fp32 K tile 32x512 (cp.async target)
#define W_SP  49664   // 4 x (32*36)
#define W_P0  54272
#define W_P1  54912
#define W_M   55552
#define W_L   55584
#define W_SC  55616
#define SMEM_WORDS 55648
#define SMEM_BYTES (SMEM_WORDS * 4)   // 222,592 B

__device__ __forceinline__ uint32_t smem_u32(const void* p) {
    uint32_t a;
    asm("{ .reg .u64 t; cvta.to.shared.u64 t, %1; cvt.u32.u64 %0, t; }" : "=r"(a) : "l"(p));
    return a;
}

__device__ __forceinline__ void cvt2(float x, float y, uint32_t& hip, uint32_t& lop) {
    __nv_bfloat16 bx = __float2bfloat16_rn(x);
    __nv_bfloat16 by = __float2bfloat16_rn(y);
    float rx = x - __bfloat162float(bx);
    float ry = y - __bfloat162float(by);
    __nv_bfloat162 h; h.x = bx; h.y = by;
    __nv_bfloat162 l; l.x = __float2bfloat16_rn(rx); l.y = __float2bfloat16_rn(ry);
    hip = *reinterpret_cast<uint32_t*>(&h);
    lop = *reinterpret_cast<uint32_t*>(&l);
}

__device__ __forceinline__ void mma16(float4& d,
                                      uint32_t a0, uint32_t a1, uint32_t a2, uint32_t a3,
                                      uint32_t b0, uint32_t b1) {
    asm volatile(
        "mma.sync.aligned.m16n8k16.row.col.f32.bf16.bf16.f32 "
        "{%0,%1,%2,%3},{%4,%5,%6,%7},{%8,%9},{%0,%1,%2,%3};"
        : "+f"(d.x), "+f"(d.y), "+f"(d.z), "+f"(d.w)
        : "r"(a0), "r"(a1), "r"(a2), "r"(a3), "r"(b0), "r"(b1));
}

__device__ __forceinline__ void ldsm4(uint32_t& r0, uint32_t& r1, uint32_t& r2, uint32_t& r3,
                                      uint32_t a) {
    asm volatile("ldmatrix.sync.aligned.m8n8.x4.shared.b16 {%0,%1,%2,%3}, [%4];"
                 : "=r"(r0), "=r"(r1), "=r"(r2), "=r"(r3) : "r"(a));
}
__device__ __forceinline__ void ldsm4t(uint32_t& r0, uint32_t& r1, uint32_t& r2, uint32_t& r3,
                                       uint32_t a) {
    asm volatile("ldmatrix.sync.aligned.m8n8.x4.trans.shared.b16 {%0,%1,%2,%3}, [%4];"
                 : "=r"(r0), "=r"(r1), "=r"(r2), "=r"(r3) : "r"(a));
}

__device__ __forceinline__ void cpasync16(uint32_t saddr, const float* g) {
    asm volatile("cp.async.cg.shared.global [%0], [%1], 16;" :: "r"(saddr), "l"(g));
}
__device__ __forceinline__ void cpasync_commit() {
    asm volatile("cp.async.commit_group;" ::: "memory");
}
__device__ __forceinline__ void cpasync_wait0() {
    asm volatile("cp.async.wait_group 0;" ::: "memory");
}

__global__ void __launch_bounds__(NT_, 1)
attn_flash_v10(const float* __restrict__ enc,
               const float* __restrict__ dec,
               float* __restrict__ out) {
    extern __shared__ uint32_t sm[];
    float* fM  = (float*)(sm + W_M);
    float* fL  = (float*)(sm + W_L);
    float* fSc = (float*)(sm + W_SC);
    float* raw = (float*)(sm + W_RAW);

    const uint32_t sb = smem_u32(sm);
    const int tid  = threadIdx.x;
    const int lane = tid & 31;
    const int wid  = tid >> 5;           // 0..7
    const int g  = lane >> 2;
    const int t  = lane & 3;
    const int l16 = lane & 15;
    const int lhi = lane >> 4;
    const int l8  = lane & 7;
    const int mi  = lane >> 3;

    const int b  = blockIdx.x >> 6;
    const int q0 = (blockIdx.x & 63) * QT;
    const float* decb = dec + ((size_t)b * SEQ + q0) * DIM;
    const float* encb = enc + (size_t)b * SEQ * DIM;

    const int wm = wid >> 2;     // GEMM1 m-half 0..1
    const int wk = wid & 3;      // GEMM1 k-slice 0..3
    const int nb = wid * 64;     // GEMM2 column slice

    // ---- prologue: stage Q (split) into buf1, init stats ----
#pragma unroll
    for (int j = 0; j < 16; j++) {
        int i  = tid + j * NT_;
        int r  = i >> 7;
        int c4 = (i & 127) << 2;
        float4 v = *(const float4*)(decb + r * DIM + c4);
        uint32_t h0, l0, h1, l1;
        cvt2(v.x, v.y, h0, l0);
        cvt2(v.z, v.w, h1, l1);
        uint32_t w = r * QS32 + (c4 >> 1);
        *(uint2*)(sm + W_B1H + w) = make_uint2(h0, h1);
        *(uint2*)(sm + W_B1L + w) = make_uint2(l0, l1);
    }
    if (tid < QT) { fM[tid] = -1e30f; fL[tid] = 0.0f; }
    __syncthreads();

    // ---- extract Q fragments into registers (64 regs) ----
    uint32_t qh[8][4], ql[8][4];
    {
        uint32_t aQh = sb + 4u * (W_B1H + (wm * 16 + l16) * QS32) + wk * 256 + lhi * 16;
        uint32_t aQl = aQh + 4u * KBW;
#pragma unroll
        for (int s = 0; s < 8; s++) {
            ldsm4(qh[s][0], qh[s][1], qh[s][2], qh[s][3], aQh + s * 32);
            ldsm4(ql[s][0], ql[s][1], ql[s][2], ql[s][3], aQl + s * 32);
        }
    }

    // ---- load K tile 0 into buf0 (direct LDG path) ----
#pragma unroll
    for (int j = 0; j < 16; j++) {
        int i  = tid + j * NT_;
        int r  = i >> 7;
        int c4 = (i & 127) << 2;
        float4 v = *(const float4*)(encb + (size_t)r * DIM + c4);
        uint32_t h0, l0, h1, l1;
        cvt2(v.x, v.y, h0, l0);
        cvt2(v.z, v.w, h1, l1);
        uint32_t w = r * QS32 + (c4 >> 1);
        *(uint2*)(sm + W_B0H + w) = make_uint2(h0, h1);
        *(uint2*)(sm + W_B0L + w) = make_uint2(l0, l1);
    }
    // ---- issue cp.async for K tile 1 -> raw ----
    {
        const float* kg = encb + (size_t)KT * DIM;
#pragma unroll
        for (int j = 0; j < 16; j++) {
            int i = tid + j * NT_;
            int r = i >> 7, c16 = i & 127;
            cpasync16(sb + 4u * W_RAW + (uint32_t)(r * 2048 + c16 * 16),
                      kg + (size_t)r * DIM + c16 * 4);
        }
        cpasync_commit();
    }
    __syncthreads();

    float4 o[2][8];
#pragma unroll
    for (int mt = 0; mt < 2; mt++)
#pragma unroll
        for (int nt = 0; nt < 8; nt++) o[mt][nt] = make_float4(0.f, 0.f, 0.f, 0.f);

    for (int it = 0; it < NIT; it++) {
        const uint32_t kb = sb + ((it & 1) ? (uint32_t)(W_B1H * 4) : 0u);

        // ---- GEMM1: S-partial[16x32] per warp over its k128 slice ----
        {
            uint32_t aBhA = kb + 4u * (((mi >> 1) * 8 + l8) * QS32) + wk * 256 + (mi & 1) * 16;
            uint32_t aBhB = aBhA + 16u * QS32 * 4;
            uint32_t aBlA = aBhA + 4u * KBW;
            uint32_t aBlB = aBhB + 4u * KBW;
            float4 cH[4], cX[4];
#pragma unroll
            for (int j = 0; j < 4; j++) {
                cH[j] = make_float4(0.f, 0.f, 0.f, 0.f);
                cX[j] = make_float4(0.f, 0.f, 0.f, 0.f);
            }
#pragma unroll
            for (int s = 0; s < 8; s++) {
                uint32_t bh0, bh1, bh2, bh3, bh4, bh5, bh6, bh7;
                uint32_t bl0, bl1, bl2, bl3, bl4, bl5, bl6, bl7;
                ldsm4(bh0, bh1, bh2, bh3, aBhA + s * 32);
                ldsm4(bh4, bh5, bh6, bh7, aBhB + s * 32);
                ldsm4(bl0, bl1, bl2, bl3, aBlA + s * 32);
                ldsm4(bl4, bl5, bl6, bl7, aBlB + s * 32);
                mma16(cH[0], qh[s][0], qh[s][1], qh[s][2], qh[s][3], bh0, bh1);
                mma16(cH[1], qh[s][0], qh[s][1], qh[s][2], qh[s][3], bh2, bh3);
                mma16(cH[2], qh[s][0], qh[s][1], qh[s][2], qh[s][3], bh4, bh5);
                mma16(cH[3], qh[s][0], qh[s][1], qh[s][2], qh[s][3], bh6, bh7);
                mma16(cX[0], qh[s][0], qh[s][1], qh[s][2], qh[s][3], bl0, bl1);
                mma16(cX[1], qh[s][0], qh[s][1], qh[s][2], qh[s][3], bl2, bl3);
                mma16(cX[2], qh[s][0], qh[s][1], qh[s][2], qh[s][3], bl4, bl5);
                mma16(cX[3], qh[s][0], qh[s][1], qh[s][2], qh[s][3], bl6, bl7);
                mma16(cX[0], ql[s][0], ql[s][1], ql[s][2], ql[s][3], bh0, bh1);
                mma16(cX[1], ql[s][0], ql[s][1], ql[s][2], ql[s][3], bh2, bh3);
                mma16(cX[2], ql[s][0], ql[s][1], ql[s][2], ql[s][3], bh4, bh5);
                mma16(cX[3], ql[s][0], ql[s][1], ql[s][2], ql[s][3], bh6, bh7);
            }
            float* sp = (float*)(sm + W_SP + wk * 1152);
            int rr = wm * 16 + g;
#pragma unroll
            for (int j = 0; j < 4; j++) {
                int cc = j * 8 + (t << 1);
                *(float2*)(sp + rr * SPST + cc) =
                    make_float2(cH[j].x + cX[j].x, cH[j].y + cX[j].y);
                *(float2*)(sp + (rr + 8) * SPST + cc) =
                    make_float2(cH[j].z + cX[j].z, cH[j].w + cX[j].w);
            }
        }
        __syncthreads();

        // ---- phase2: softmax + convert raw -> buf[(it+1)&1] ----
        {
            cpasync_wait0();

            int row = tid >> 3;
            int c4s = (tid & 7) << 2;
            const float* spb = (const float*)(sm + W_SP) + row * SPST + c4s;
            float4 u0 = *(const float4*)(spb);
            float4 u1 = *(const float4*)(spb + 1152);
            float4 u2 = *(const float4*)(spb + 2304);
            float4 u3 = *(const float4*)(spb + 3456);
            float s0 = (u0.x + u1.x) + (u2.x + u3.x);
            float s1 = (u0.y + u1.y) + (u2.y + u3.y);
            float s2 = (u0.z + u1.z) + (u2.z + u3.z);
            float s3 = (u0.w + u1.w) + (u2.w + u3.w);
            float mx = fmaxf(fmaxf(s0, s1), fmaxf(s2, s3));
            mx = fmaxf(mx, __shfl_xor_sync(0xffffffffu, mx, 1));
            mx = fmaxf(mx, __shfl_xor_sync(0xffffffffu, mx, 2));
            mx = fmaxf(mx, __shfl_xor_sync(0xffffffffu, mx, 4));
            float mo = fM[row];
            float mn = fmaxf(mo, mx);
            float p0 = __expf(s0 - mn), p1 = __expf(s1 - mn);
            float p2 = __expf(s2 - mn), p3 = __expf(s3 - mn);
            float su = (p0 + p1) + (p2 + p3);
            su += __shfl_xor_sync(0xffffffffu, su, 1);
            su += __shfl_xor_sync(0xffffffffu, su, 2);
            su += __shfl_xor_sync(0xffffffffu, su, 4);
            if ((tid & 7) == 0) {
                float sc = __expf(mo - mn);
                fSc[row] = sc;
                fM[row]  = mn;
                fL[row]  = fL[row] * sc + su;
            }
            uint32_t h0, l0, h1, l1;
            cvt2(p0, p1, h0, l0);
            cvt2(p2, p3, h1, l1);
            uint32_t w = row * PS + ((tid & 7) << 1);
            *(uint2*)(sm + W_P0 + w) = make_uint2(h0, h1);
            *(uint2*)(sm + W_P1 + w) = make_uint2(l0, l1);

            if (it + 1 < NIT) {
                uint32_t* kd = sm + (((it + 1) & 1) ? W_B1H : W_B0H);
#pragma unroll
                for (int j = 0; j < 16; j++) {
                    int i = tid + j * NT_;
                    int r = i >> 7, c16 = i & 127;
                    float4 v = *(const float4*)(raw + r * 512 + c16 * 4);
                    uint32_t hh0, ll0, hh1, ll1;
                    cvt2(v.x, v.y, hh0, ll0);
                    cvt2(v.z, v.w, hh1, ll1);
                    uint32_t ww = r * QS32 + c16 * 2;
                    *(uint2*)(kd + ww) = make_uint2(hh0, hh1);
                    *(uint2*)(kd + KBW + ww) = make_uint2(ll0, ll1);
                }
            }
        }
        __syncthreads();

        // ---- issue cp.async for K(it+2) (raw free: all reads done) ----
        if (it + 2 < NIT) {
            const float* kg = encb + (size_t)(it + 2) * KT * DIM;
#pragma unroll
            for (int j = 0; j < 16; j++) {
                int i = tid + j * NT_;
                int r = i >> 7, c16 = i & 127;
                cpasync16(sb + 4u * W_RAW + (uint32_t)(r * 2048 + c16 * 16),
                          kg + (size_t)r * DIM + c16 * 4);
            }
            cpasync_commit();
        }

        // ---- rescale O ----
        {
            float sc[4];
#pragma unroll
            for (int j = 0; j < 4; j++) sc[j] = fSc[g + 8 * j];
#pragma unroll
            for (int mt = 0; mt < 2; mt++) {
                float slo = sc[2 * mt], shi = sc[2 * mt + 1];
#pragma unroll
                for (int nt = 0; nt < 8; nt++) {
                    o[mt][nt].x *= slo; o[mt][nt].y *= slo;
                    o[mt][nt].z *= shi; o[mt][nt].w *= shi;
                }
            }
        }

        // ---- GEMM2: O[32 x 64/warp] += P[32x32] @ E[32x512] ----
        {
            uint32_t aP0 = sb + 4u * (W_P0 + l16 * PS) + lhi * 16;
            uint32_t aP1 = aP0 + 4u * (W_P1 - W_P0);
            uint32_t aE0 = kb + 4u * (l16 * QS32) + (uint32_t)nb * 2 + lhi * 16;
            uint32_t aE1 = aE0 + 4u * KBW;
#pragma unroll
            for (int ks = 0; ks < 2; ks++) {
                uint32_t A0[2][4], A1[2][4];
#pragma unroll
                for (int mt = 0; mt < 2; mt++) {
                    uint32_t off = (uint32_t)(mt * 16 * PS + ks * 8) * 4;
                    ldsm4(A0[mt][0], A0[mt][1], A0[mt][2], A0[mt][3], aP0 + off);
                    ldsm4(A1[mt][0], A1[mt][1], A1[mt][2], A1[mt][3], aP1 + off);
                }
                uint32_t eoff = (uint32_t)(ks * 16 * QS32) * 4;
#pragma unroll
                for (int ntp = 0; ntp < 4; ntp++) {
                    uint32_t bh0, bh1, bh2, bh3, bl0, bl1, bl2, bl3;
                    ldsm4t(bh0, bh1, bh2, bh3, aE0 + eoff + ntp * 32);
                    ldsm4t(bl0, bl1, bl2, bl3, aE1 + eoff + ntp * 32);
                    int n0 = ntp * 2, n1 = ntp * 2 + 1;
#pragma unroll
                    for (int mt = 0; mt < 2; mt++) {
                        mma16(o[mt][n0], A0[mt][0], A0[mt][1], A0[mt][2], A0[mt][3], bl0, bl1);
                        mma16(o[mt][n0], A1[mt][0], A1[mt][1], A1[mt][2], A1[mt][3], bh0, bh1);
                        mma16(o[mt][n0], A0[mt][0], A0[mt][1], A0[mt][2], A0[mt][3], bh0, bh1);
                        mma16(o[mt][n1], A0[mt][0], A0[mt][1], A0[mt][2], A0[mt][3], bl2, bl3);
                        mma16(o[mt][n1], A1[mt][0], A1[mt][1], A1[mt][2], A1[mt][3], bh2, bh3);
                        mma16(o[mt][n1], A0[mt][0], A0[mt][1], A0[mt][2], A0[mt][3], bh2, bh3);
                    }
                }
            }
        }
    }

    __syncthreads();

    // ---- epilogue: normalize by 1/l and store ----
    {
        float il[4];
#pragma unroll
        for (int j = 0; j < 4; j++) il[j] = 1.0f / fL[g + 8 * j];
        float* ob = out + ((size_t)b * SEQ + q0) * DIM;
#pragma unroll
        for (int mt = 0; mt < 2; mt++) {
            float ilo = il[2 * mt], ihi = il[2 * mt + 1];
            int r = mt * 16 + g;
#pragma unroll
            for (int nt = 0; nt < 8; nt++) {
                int c = nb + nt * 8 + (t << 1);
                float2 v0 = make_float2(o[mt][nt].x * ilo, o[mt][nt].y * ilo);
                float2 v1 = make_float2(o[mt][nt].z * ihi, o[mt][nt].w * ihi);
                *(float2*)(ob + r * DIM + c)       = v0;
                *(float2*)(ob + (r + 8) * DIM + c) = v1;
            }
        }
    }
}

extern "C" void kernel_launch(void* const* d_in, const int* in_sizes, int n_in,
                              void* d_out, int out_size) {
    const float* enc = (const float*)d_in[0];   // enc_outputs [8,2048,512]
    const float* dec = (const float*)d_in[1];   // dec_outputs [8,2048,512]
    float* out = (float*)d_out;                 // [8,2048,512]

    cudaFuncSetAttribute(attn_flash_v10,
                         cudaFuncAttributeMaxDynamicSharedMemorySize, SMEM_BYTES);

    dim3 grid(8 * (SEQ / QT));   // 512 CTAs, 1 per SM
    attn_flash_v10<<<grid, NT_, SMEM_BYTES>>>(enc, dec, out);
}